// round 6
// baseline (speedup 1.0000x reference)
#include <cuda_runtime.h>

#define KK 16
#define LL 64
#define BB 32768
#define ROWF4 256   // 64 digits * 4 float4 per element row

typedef unsigned long long u64t;

__device__ __forceinline__ u64t pk2(float lo, float hi) {
    u64t r; asm("mov.b64 %0, {%1, %2};" : "=l"(r) : "f"(lo), "f"(hi)); return r;
}
__device__ __forceinline__ void upk2(float& lo, float& hi, u64t v) {
    asm("mov.b64 {%0, %1}, %2;" : "=f"(lo), "=f"(hi) : "l"(v));
}
__device__ __forceinline__ u64t fma2(u64t a, u64t b, u64t c) {
    u64t d; asm("fma.rn.f32x2 %0, %1, %2, %3;" : "=l"(d) : "l"(a), "l"(b), "l"(c)); return d;
}

// One warp per block; lane owns one batch element; both roles per thread.
__global__ __launch_bounds__(32) void bitop_kernel(
    const float4* __restrict__ op1, const float4* __restrict__ op2,
    float4* __restrict__ outa, float4* __restrict__ outs)
{
    __shared__ float4 sin[2][2][32][5];   // [buf][tensor][elem][slot], pad 5
    __shared__ float4 sout[2][32][5];     // [tensor][elem][slot]

    const int ln = threadIdx.x;
    const int ebase = blockIdx.x * 32;

    const int k  = ln & 3;    // slot within digit
    const int g0 = ln >> 2;   // staging element base (0..7)

    size_t srow[4];
    #pragma unroll
    for (int r = 0; r < 4; ++r)
        srow[r] = (size_t)(ebase + g0 + 8 * r) * ROWF4;

    // prologue: stage digit 0
    #pragma unroll
    for (int r = 0; r < 4; ++r) {
        sin[0][0][g0 + 8 * r][k] = op1[srow[r] + k];
        sin[0][1][g0 + 8 * r][k] = op2[srow[r] + k];
    }
    __syncwarp();

    float sta = 0.f, sts = 0.f;
    int buf = 0;
    float4 pf[8];

    #pragma unroll 1
    for (int l = 0; l < LL; ++l) {
        float4 A0 = sin[buf][0][ln][0], A1 = sin[buf][0][ln][1],
               A2 = sin[buf][0][ln][2], A3 = sin[buf][0][ln][3];
        float4 B0 = sin[buf][1][ln][0], B1 = sin[buf][1][ln][1],
               B2 = sin[buf][1][ln][2], B3 = sin[buf][1][ln][3];

        // prefetch next digit (coalesced), hidden by compute below
        if (l < LL - 1) {
            const size_t off = (size_t)(l + 1) * 4 + k;
            #pragma unroll
            for (int r = 0; r < 4; ++r) {
                pf[2 * r]     = op1[srow[r] + off];
                pf[2 * r + 1] = op2[srow[r] + off];
            }
        }

        float a[16] = {A0.x,A0.y,A0.z,A0.w, A1.x,A1.y,A1.z,A1.w,
                       A2.x,A2.y,A2.z,A2.w, A3.x,A3.y,A3.z,A3.w};
        float c[16] = {B0.x,B0.y,B0.z,B0.w, B1.x,B1.y,B1.z,B1.w,
                       B2.x,B2.y,B2.z,B2.w, B3.x,B3.y,B3.z,B3.w};

        // scalar side work first (frees a for packing)
        float Csuf[16];
        Csuf[15] = c[15];
        #pragma unroll
        for (int m = 14; m >= 1; --m) Csuf[m] = Csuf[m + 1] + c[m];
        float Sa = 0.f, Ss = 0.f;
        #pragma unroll
        for (int i = 1; i < 16; ++i)  Sa = fmaf(a[i], Csuf[16 - i], Sa);  // P(i+j>=16)
        #pragma unroll
        for (int i = 0; i < 15; ++i)  Ss = fmaf(a[i], Csuf[i + 1], Ss);   // P(i<j)

        // packed operands: even- and odd-aligned a pairs
        u64t ae[8], ao[8];
        #pragma unroll
        for (int u = 0; u < 8; ++u) {
            ae[u] = pk2(a[2 * u], a[2 * u + 1]);
            ao[u] = pk2(a[2 * u + 1], a[(2 * u + 2) & 15]);
        }

        // packed cyclic conv (add) + corr (sub): 256 FFMA2 total
        u64t Qa[8], Qs[8];
        #pragma unroll
        for (int u = 0; u < 8; ++u) { Qa[u] = 0ull; Qs[u] = 0ull; }

        #pragma unroll
        for (int m = 0; m < 8; ++m) {
            const u64t ce = pk2(c[2 * m],     c[2 * m]);      // j = 2m
            const u64t co = pk2(c[2 * m + 1], c[2 * m + 1]);  // j = 2m+1
            #pragma unroll
            for (int u = 0; u < 8; ++u) {
                Qa[(u + m) & 7]     = fma2(ae[u], ce, Qa[(u + m) & 7]);
                Qa[(u + m + 1) & 7] = fma2(ao[u], co, Qa[(u + m + 1) & 7]);
                Qs[(u - m) & 7]     = fma2(ae[u], ce, Qs[(u - m) & 7]);
                Qs[(u - m) & 7]     = fma2(ao[u], co, Qs[(u - m) & 7]);
            }
        }

        float qa[16], qs[16];
        #pragma unroll
        for (int u = 0; u < 8; ++u) {
            upk2(qa[2 * u], qa[2 * u + 1], Qa[u]);
            upk2(qs[2 * u], qs[2 * u + 1], Qs[u]);
        }

        float ra[16], rs[16];
        #pragma unroll
        for (int v = 0; v < 16; ++v) {
            ra[v] = fmaf(sta, qa[(v + 15) & 15] - qa[v], qa[v]);
            rs[v] = fmaf(sts, qs[(v + 1)  & 15] - qs[v], qs[v]);
        }
        sta = fmaf(sta, qa[15], Sa);
        sts = fmaf(sts, qs[0],  Ss);

        // stage next digit input (LDG long complete)
        if (l < LL - 1) {
            #pragma unroll
            for (int r = 0; r < 4; ++r) {
                sin[buf ^ 1][0][g0 + 8 * r][k] = pf[2 * r];
                sin[buf ^ 1][1][g0 + 8 * r][k] = pf[2 * r + 1];
            }
        }

        // stage outputs
        sout[0][ln][0] = make_float4(ra[0],  ra[1],  ra[2],  ra[3]);
        sout[0][ln][1] = make_float4(ra[4],  ra[5],  ra[6],  ra[7]);
        sout[0][ln][2] = make_float4(ra[8],  ra[9],  ra[10], ra[11]);
        sout[0][ln][3] = make_float4(ra[12], ra[13], ra[14], ra[15]);
        sout[1][ln][0] = make_float4(rs[0],  rs[1],  rs[2],  rs[3]);
        sout[1][ln][1] = make_float4(rs[4],  rs[5],  rs[6],  rs[7]);
        sout[1][ln][2] = make_float4(rs[8],  rs[9],  rs[10], rs[11]);
        sout[1][ln][3] = make_float4(rs[12], rs[13], rs[14], rs[15]);
        __syncwarp();

        // coalesced stores
        const size_t soff = (size_t)l * 4 + k;
        #pragma unroll
        for (int r = 0; r < 4; ++r) {
            outa[srow[r] + soff] = sout[0][g0 + 8 * r][k];
            outs[srow[r] + soff] = sout[1][g0 + 8 * r][k];
        }
        __syncwarp();   // protect sout/sin[buf^1] before next iteration rewrites

        buf ^= 1;
    }
}

extern "C" void kernel_launch(void* const* d_in, const int* in_sizes, int n_in,
                              void* d_out, int out_size)
{
    const float4* op1 = (const float4*)d_in[0];
    const float4* op2 = (const float4*)d_in[1];
    float* out = (float*)d_out;
    float4* outa = (float4*)out;
    float4* outs = (float4*)(out + (size_t)BB * LL * KK);

    bitop_kernel<<<BB / 32, 32>>>(op1, op2, outa, outs);
}

// round 7
// speedup vs baseline: 1.1239x; 1.1239x over previous
#include <cuda_runtime.h>

#define KK 16
#define LL 64
#define BB 32768
#define ROWF4 256          // 256 float4 per element row
#define NPAIR (LL / 2)     // 32 digit pairs

__device__ __forceinline__ void cp16(unsigned dst, const float4* src) {
    asm volatile("cp.async.cg.shared.global [%0], [%1], 16;\n" :: "r"(dst), "l"(src));
}

// One warp per block; lane owns one batch element (both roles).
// I/O at digit-pair (128B) granularity: 8 lanes cover one element's pair.
__global__ __launch_bounds__(32) void bitop_kernel(
    const float4* __restrict__ op1, const float4* __restrict__ op2,
    float4* __restrict__ outa, float4* __restrict__ outs)
{
    __shared__ float4 sin[2][2][32][9];   // [buf][tensor][elem][8 slots + pad]
    __shared__ float4 sou[2][32][9];      // [tensor][elem][8 slots + pad]

    const int ln = threadIdx.x;
    const int ebase = blockIdx.x * 32;
    const int q = ln & 7;    // 16B slot within the 128B pair-chunk
    const int g = ln >> 3;   // element sub-group 0..3

    unsigned sb00 = (unsigned)__cvta_generic_to_shared(&sin[0][0][0][q]);
    unsigned sb01 = (unsigned)__cvta_generic_to_shared(&sin[0][1][0][q]);
    unsigned sb10 = (unsigned)__cvta_generic_to_shared(&sin[1][0][0][q]);
    unsigned sb11 = (unsigned)__cvta_generic_to_shared(&sin[1][1][0][q]);

    // ---- stage pair p into buffer b (16 cp.async, all full-line) ----
    #define STAGE(b, p)                                                        \
        do {                                                                   \
            const unsigned d0 = (b) ? sb10 : sb00;                             \
            const unsigned d1 = (b) ? sb11 : sb01;                             \
            _Pragma("unroll")                                                  \
            for (int r = 0; r < 8; ++r) {                                      \
                const int e = g + 4 * r;                                       \
                const size_t gi = (size_t)(ebase + e) * ROWF4                  \
                                + (size_t)(p) * 8 + q;                         \
                cp16(d0 + e * 144, op1 + gi);                                  \
                cp16(d1 + e * 144, op2 + gi);                                  \
            }                                                                  \
            asm volatile("cp.async.commit_group;\n" ::);                       \
        } while (0)

    STAGE(0, 0);

    float sta = 0.f, sts = 0.f;   // carry1 / borrow1
    int buf = 0;

    #pragma unroll 1
    for (int p = 0; p < NPAIR; ++p) {
        if (p < NPAIR - 1) {
            STAGE(buf ^ 1, p + 1);
            asm volatile("cp.async.wait_group 1;\n" ::);
        } else {
            asm volatile("cp.async.wait_group 0;\n" ::);
        }
        __syncwarp();

        #pragma unroll 1
        for (int d = 0; d < 2; ++d) {
            const int s = d * 4;
            float4 A0 = sin[buf][0][ln][s+0], A1 = sin[buf][0][ln][s+1],
                   A2 = sin[buf][0][ln][s+2], A3 = sin[buf][0][ln][s+3];
            float4 B0 = sin[buf][1][ln][s+0], B1 = sin[buf][1][ln][s+1],
                   B2 = sin[buf][1][ln][s+2], B3 = sin[buf][1][ln][s+3];

            float a[16] = {A0.x,A0.y,A0.z,A0.w, A1.x,A1.y,A1.z,A1.w,
                           A2.x,A2.y,A2.z,A2.w, A3.x,A3.y,A3.z,A3.w};
            float c[16] = {B0.x,B0.y,B0.z,B0.w, B1.x,B1.y,B1.z,B1.w,
                           B2.x,B2.y,B2.z,B2.w, B3.x,B3.y,B3.z,B3.w};

            // cyclic conv (add) + cyclic corr (sub)
            float Qa[16], Qs[16];
            #pragma unroll
            for (int v = 0; v < 16; ++v) { Qa[v] = 0.f; Qs[v] = 0.f; }
            #pragma unroll
            for (int i = 0; i < 16; ++i) {
                #pragma unroll
                for (int j = 0; j < 16; ++j) {
                    Qa[(i + j) & 15]      = fmaf(a[i], c[j], Qa[(i + j) & 15]);
                    Qs[(i - j + 16) & 15] = fmaf(a[i], c[j], Qs[(i - j + 16) & 15]);
                }
            }

            float Csuf[16];
            Csuf[15] = c[15];
            #pragma unroll
            for (int m = 14; m >= 1; --m) Csuf[m] = Csuf[m + 1] + c[m];

            float Sa = 0.f, Ss = 0.f;
            #pragma unroll
            for (int i = 1; i < 16; ++i)  Sa = fmaf(a[i], Csuf[16 - i], Sa); // P(i+j>=16)
            #pragma unroll
            for (int i = 0; i < 15; ++i)  Ss = fmaf(a[i], Csuf[i + 1], Ss);  // P(i<j)

            float ra[16], rs[16];
            #pragma unroll
            for (int v = 0; v < 16; ++v) {
                ra[v] = fmaf(sta, Qa[(v + 15) & 15] - Qa[v], Qa[v]);
                rs[v] = fmaf(sts, Qs[(v + 1)  & 15] - Qs[v], Qs[v]);
            }
            sta = fmaf(sta, Qa[15], Sa);
            sts = fmaf(sts, Qs[0],  Ss);

            sou[0][ln][s+0] = make_float4(ra[0],  ra[1],  ra[2],  ra[3]);
            sou[0][ln][s+1] = make_float4(ra[4],  ra[5],  ra[6],  ra[7]);
            sou[0][ln][s+2] = make_float4(ra[8],  ra[9],  ra[10], ra[11]);
            sou[0][ln][s+3] = make_float4(ra[12], ra[13], ra[14], ra[15]);
            sou[1][ln][s+0] = make_float4(rs[0],  rs[1],  rs[2],  rs[3]);
            sou[1][ln][s+1] = make_float4(rs[4],  rs[5],  rs[6],  rs[7]);
            sou[1][ln][s+2] = make_float4(rs[8],  rs[9],  rs[10], rs[11]);
            sou[1][ln][s+3] = make_float4(rs[12], rs[13], rs[14], rs[15]);
        }
        __syncwarp();

        // full-line coalesced stores of the whole pair
        const size_t so = (size_t)p * 8 + q;
        #pragma unroll
        for (int r = 0; r < 8; ++r) {
            const int e = g + 4 * r;
            const size_t gi = (size_t)(ebase + e) * ROWF4 + so;
            outa[gi] = sou[0][e][q];
            outs[gi] = sou[1][e][q];
        }
        __syncwarp();   // sou reads complete before next iteration overwrites

        buf ^= 1;
    }
    #undef STAGE
}

extern "C" void kernel_launch(void* const* d_in, const int* in_sizes, int n_in,
                              void* d_out, int out_size)
{
    const float4* op1 = (const float4*)d_in[0];
    const float4* op2 = (const float4*)d_in[1];
    float* out = (float*)d_out;
    float4* outa = (float4*)out;
    float4* outs = (float4*)(out + (size_t)BB * LL * KK);

    bitop_kernel<<<BB / 32, 32>>>(op1, op2, outa, outs);
}

// round 8
// speedup vs baseline: 1.1974x; 1.0654x over previous
#include <cuda_runtime.h>

#define KK 16
#define LL 64
#define BB 32768
#define ROWF4 256          // 256 float4 per element row
#define NPAIR (LL / 2)     // 32 digit pairs

__device__ __forceinline__ void cp16(unsigned dst, const float4* src) {
    asm volatile("cp.async.cg.shared.global [%0], [%1], 16;\n" :: "r"(dst), "l"(src));
}

// One warp per block, 16 elements per warp.
// Lanes 0-15: add role, lanes 16-31: sub role (same element index ln&15).
// Fully warp-uniform math: sub is mapped onto the add convolution by
// reversing c and tracking the complement state t = borrow0.
__global__ __launch_bounds__(32) void bitop_kernel(
    const float4* __restrict__ op1, const float4* __restrict__ op2,
    float4* __restrict__ outa, float4* __restrict__ outs)
{
    // rows 0-15: op1 elems 0-15; rows 16-31: op2 elems 0-15. pad to 9 slots.
    __shared__ float4 sin[2][32][9];
    __shared__ float4 sou[32][9];   // row = role*16 + elem = ln

    const int ln   = threadIdx.x;
    const int role = ln >> 4;       // 0 = add, 1 = sub
    const int em   = ln & 15;
    const int ebase = blockIdx.x * 16;

    const int q = ln & 7;           // 16B slot within 128B pair chunk
    const int g = ln >> 3;          // 0..3

    // staging rows g+4r, r=0..7: r<4 -> op1/outa elem g+4r; r>=4 -> op2/outs elem g+4(r-4)
    unsigned goff[8];
    #pragma unroll
    for (int r = 0; r < 8; ++r) {
        const int elem = (r < 4) ? (g + 4 * r) : (g + 4 * (r - 4));
        goff[r] = (unsigned)(ebase + elem) * ROWF4;
    }

    unsigned sb[2];
    sb[0] = (unsigned)__cvta_generic_to_shared(&sin[0][0][0]);
    sb[1] = (unsigned)__cvta_generic_to_shared(&sin[1][0][0]);

    #define STAGE(b, p)                                                       \
        do {                                                                  \
            _Pragma("unroll")                                                 \
            for (int r = 0; r < 8; ++r) {                                     \
                const float4* src = ((r < 4) ? op1 : op2)                     \
                                  + goff[r] + (size_t)(p) * 8 + q;            \
                cp16(sb[b] + (g + 4 * r) * 144 + q * 16, src);                \
            }                                                                 \
            asm volatile("cp.async.commit_group;\n" ::);                      \
        } while (0)

    STAGE(0, 0);

    // state: add lanes t = carry1 (init 0); sub lanes t = borrow0 (init 1)
    float t = role ? 1.f : 0.f;
    int buf = 0;

    #pragma unroll 1
    for (int p = 0; p < NPAIR; ++p) {
        if (p < NPAIR - 1) {
            STAGE(buf ^ 1, p + 1);
            asm volatile("cp.async.wait_group 1;\n" ::);
        } else {
            asm volatile("cp.async.wait_group 0;\n" ::);
        }
        __syncwarp();

        #pragma unroll 1
        for (int d = 0; d < 2; ++d) {
            const int s = d * 4;
            float4 A0 = sin[buf][em][s+0],      A1 = sin[buf][em][s+1],
                   A2 = sin[buf][em][s+2],      A3 = sin[buf][em][s+3];
            float4 B0 = sin[buf][16+em][s+0],   B1 = sin[buf][16+em][s+1],
                   B2 = sin[buf][16+em][s+2],   B3 = sin[buf][16+em][s+3];

            float a[16] = {A0.x,A0.y,A0.z,A0.w, A1.x,A1.y,A1.z,A1.w,
                           A2.x,A2.y,A2.z,A2.w, A3.x,A3.y,A3.z,A3.w};
            float c[16] = {B0.x,B0.y,B0.z,B0.w, B1.x,B1.y,B1.z,B1.w,
                           B2.x,B2.y,B2.z,B2.w, B3.x,B3.y,B3.z,B3.w};

            // suffix sums of original c
            float Csuf[16];
            Csuf[15] = c[15];
            #pragma unroll
            for (int m = 14; m >= 1; --m) Csuf[m] = Csuf[m + 1] + c[m];

            // S: add = P(i+j>=16), sub = P(i<j); role-uniform selects
            float S = 0.f;
            #pragma unroll
            for (int i = 0; i < 16; ++i) {
                const float cA = (i >= 1)  ? Csuf[16 - i] : 0.f;
                const float cS = (i <= 14) ? Csuf[i + 1]  : 0.f;
                S = fmaf(a[i], role ? cS : cA, S);
            }

            // sub lanes: reverse c  (c'[j] = c[15-j]) -> conv computes Qs[(v+1)&15]
            #pragma unroll
            for (int j = 0; j < 8; ++j) {
                const float lo = c[j], hi = c[15 - j];
                c[j]      = role ? hi : lo;
                c[15 - j] = role ? lo : hi;
            }

            // shared cyclic convolution (256 FMA)
            float X[16];
            #pragma unroll
            for (int v = 0; v < 16; ++v) X[v] = 0.f;
            #pragma unroll
            for (int i = 0; i < 16; ++i) {
                #pragma unroll
                for (int j = 0; j < 16; ++j)
                    X[(i + j) & 15] = fmaf(a[i], c[j], X[(i + j) & 15]);
            }

            // unified output: res[v] = (1-t)*X[v] + t*X[(v-1)&15]
            float res[16];
            #pragma unroll
            for (int v = 0; v < 16; ++v)
                res[v] = fmaf(t, X[(v + 15) & 15] - X[v], X[v]);

            // unified state: t' = base + t * X[15]
            const float base = role ? (1.f - S - X[15]) : S;
            t = fmaf(t, X[15], base);

            sou[ln][s+0] = make_float4(res[0],  res[1],  res[2],  res[3]);
            sou[ln][s+1] = make_float4(res[4],  res[5],  res[6],  res[7]);
            sou[ln][s+2] = make_float4(res[8],  res[9],  res[10], res[11]);
            sou[ln][s+3] = make_float4(res[12], res[13], res[14], res[15]);
        }
        __syncwarp();

        // full-128B coalesced stores: rows g+4r; r<4 -> outa, r>=4 -> outs
        #pragma unroll
        for (int r = 0; r < 8; ++r) {
            float4* dst = ((r < 4) ? outa : outs)
                        + goff[r] + (size_t)p * 8 + q;
            *dst = sou[g + 4 * r][q];
        }
        __syncwarp();   // sou reads & sin[buf] reads done before overwrite

        buf ^= 1;
    }
    #undef STAGE
}

extern "C" void kernel_launch(void* const* d_in, const int* in_sizes, int n_in,
                              void* d_out, int out_size)
{
    const float4* op1 = (const float4*)d_in[0];
    const float4* op2 = (const float4*)d_in[1];
    float* out = (float*)d_out;
    float4* outa = (float4*)out;
    float4* outs = (float4*)(out + (size_t)BB * LL * KK);

    bitop_kernel<<<BB / 16, 32>>>(op1, op2, outa, outs);
}